// round 14
// baseline (speedup 1.0000x reference)
#include <cuda_runtime.h>
#include <cuda_fp16.h>
#include <math.h>
#include <stdint.h>

#define DIMD 1024
#define NH   16
#define HD   64

// ---------------- scratch (device globals: no allocation allowed) ----------
__device__ __half g_Xh[16384 * 1024];          // x fp16
__device__ __half g_Wh[4 * 1024 * 1024];       // Wq|Wk|Wv|Wo fp16
__device__ __half g_Qh[16384 * 1024];          // phi(Q) fp16
__device__ __half g_Kh[16384 * 1024];          // phi(K) fp16
__device__ __half g_Vh[16384 * 1024];          // V fp16
__device__ __half g_Ah[16384 * 1024];          // attn out fp16
__device__ float  g_KVpart[64 * 8 * 64 * 64];  // [bh][chunk][d][e] fp32 partials
__device__ float  g_Zpart [64 * 8 * 64];       // [bh][chunk][d]
__device__ __half g_KVZ[64 * 72 * 64];         // [bh][e-row 0..71][d] fp16

// ---------------- convert inputs to fp16 ------------------------------------
__global__ void cvt_kernel(const float* __restrict__ x,
                           const float* __restrict__ wq, const float* __restrict__ wk,
                           const float* __restrict__ wv, const float* __restrict__ wo,
                           __half* __restrict__ xh, __half* __restrict__ wh)
{
    int i = blockIdx.x * blockDim.x + threadIdx.x;
    const int XP = 8388608, WP = 524288;
    if (i < XP) {
        float2 v = ((const float2*)x)[i];
        ((__half2*)xh)[i] = __floats2half2_rn(v.x, v.y);
    } else {
        int j = i - XP;
        int sel = j / WP, off = j - sel * WP;
        const float* src = (sel == 0) ? wq : (sel == 1) ? wk : (sel == 2) ? wv : wo;
        float2 v = ((const float2*)src)[off];
        ((__half2*)(wh))[sel * WP + off] = __floats2half2_rn(v.x, v.y);
    }
}

// ---------------- KVZ build: sum 8 chunk partials, transpose, append Z ------
__global__ void kvz_kernel(const float* __restrict__ KVpart,
                           const float* __restrict__ Zpart,
                           __half* __restrict__ KVZ)
{
    int i = blockIdx.x * blockDim.x + threadIdx.x;   // 64*72*64
    if (i >= 64 * 72 * 64) return;
    int d  = i & 63;
    int r  = (i >> 6) % 72;
    int bh = i / (72 * 64);
    float v = 0.0f;
    if (r < 64) {
#pragma unroll
        for (int c = 0; c < 8; c++)
            v += KVpart[(((size_t)bh * 8 + c) * 64 + d) * 64 + r];
    } else if (r == 64) {
#pragma unroll
        for (int c = 0; c < 8; c++)
            v += Zpart[((size_t)bh * 8 + c) * 64 + d];
    }
    KVZ[i] = __float2half(v);
}

// ---------------- asm helpers ------------------------------------------------
__device__ __forceinline__ uint32_t smem_u32(const void* p) {
    uint32_t a;
    asm("{ .reg .u64 t; cvta.to.shared.u64 t, %1; cvt.u32.u64 %0, t; }"
        : "=r"(a) : "l"(p));
    return a;
}

#define CP_ASYNC16(dst, src) \
    asm volatile("cp.async.cg.shared.global [%0], [%1], 16;" :: "r"(dst), "l"(src))
#define CP_COMMIT() asm volatile("cp.async.commit_group;" ::: "memory")
#define CP_WAIT(n)  asm volatile("cp.async.wait_group %0;" :: "n"(n) : "memory")

#define LDSM_X4(r0, r1, r2, r3, addr) \
    asm volatile("ldmatrix.sync.aligned.m8n8.x4.shared.b16 {%0,%1,%2,%3}, [%4];" \
                 : "=r"(r0), "=r"(r1), "=r"(r2), "=r"(r3) : "r"(addr))
#define LDSM_X4T(r0, r1, r2, r3, addr) \
    asm volatile("ldmatrix.sync.aligned.m8n8.x4.trans.shared.b16 {%0,%1,%2,%3}, [%4];" \
                 : "=r"(r0), "=r"(r1), "=r"(r2), "=r"(r3) : "r"(addr))

__device__ __forceinline__ void mma_f16(float* d, const uint32_t* a,
                                        uint32_t b0, uint32_t b1) {
    asm volatile(
        "mma.sync.aligned.m16n8k16.row.col.f32.f16.f16.f32 "
        "{%0,%1,%2,%3}, {%4,%5,%6,%7}, {%8,%9}, {%0,%1,%2,%3};"
        : "+f"(d[0]), "+f"(d[1]), "+f"(d[2]), "+f"(d[3])
        : "r"(a[0]), "r"(a[1]), "r"(a[2]), "r"(a[3]), "r"(b0), "r"(b1));
}

// ---------------- fp16 GEMM: 128x128x32 CTA, 4 warps, 64x64 warp tile -------
// R11 pipeline (4-stage, CP_WAIT(2)) + intra-tile ks register double-buffer:
// LDSM(ks1) sandwiched between mma halves of ks0.
constexpr int BM = 128, BN = 128, BK = 32;
constexpr int ROWB   = 80;                       // 64B data + 16B pad per row
constexpr int A_STG  = BM * ROWB;                // 10240 B
constexpr int STAGE  = 2 * A_STG;                // 20480 B
constexpr int NSTAGE = 4;
constexpr int SMEM_GEMM = NSTAGE * STAGE;        // 81920 B
constexpr int GTHREADS  = 128;

template <int OUTH>
__device__ __forceinline__
void gemm_body(const __half* __restrict__ A, const __half* __restrict__ W,
               const float* __restrict__ bias, void* __restrict__ Cv,
               int act, int bm, int bn, char* smem)
{
    const uint32_t sbase = smem_u32(smem);
    const int tid  = threadIdx.x;
    const int lane = tid & 31;
    const int warp = tid >> 5;     // 0..3
    const int wm   = warp & 1;     // 64-row slab
    const int wn   = warp >> 1;    // 64-col slab
    const int g    = lane >> 2, t4 = lane & 3;

    const __half* Arow0 = A + (size_t)bm * DIMD;
    const __half* Wrow0 = W + (size_t)bn * DIMD;

    const int a_r = (lane & 7) + ((lane >> 3) & 1) * 8;
    const int a_k = ((lane >> 4) & 1) * 8;
    const uint32_t a_off = (uint32_t)((wm * 64 + a_r) * ROWB + a_k * 2);
    const int b_r = (lane & 7) + ((lane >> 4) & 1) * 8;
    const int b_k = ((lane >> 3) & 1) * 8;
    const uint32_t b_off = (uint32_t)((wn * 64 + b_r) * ROWB + b_k * 2);

    float acc[4][8][4];
#pragma unroll
    for (int mt = 0; mt < 4; mt++)
#pragma unroll
        for (int nt = 0; nt < 8; nt++)
#pragma unroll
            for (int r = 0; r < 4; r++) acc[mt][nt][r] = 0.0f;

    const int NT = DIMD / BK;   // 32

    // staging: 512 chunks per operand, 128 threads -> 4 each
#pragma unroll
    for (int t = 0; t < 3; t++) {
        uint32_t sa = sbase + t * STAGE;
#pragma unroll
        for (int l = 0; l < 4; l++) {
            int c = tid + GTHREADS * l, row = c >> 2, kc = c & 3;
            CP_ASYNC16(sa + row * ROWB + kc * 16,
                       Arow0 + (size_t)row * DIMD + t * BK + kc * 8);
            CP_ASYNC16(sa + A_STG + row * ROWB + kc * 16,
                       Wrow0 + (size_t)row * DIMD + t * BK + kc * 8);
        }
        CP_COMMIT();
    }

    for (int t = 0; t < NT; t++) {
        CP_WAIT(2);
        __syncthreads();

        const uint32_t sa = sbase + (t & 3) * STAGE;
        const uint32_t sb = sa + A_STG;

        uint32_t ar[2][4][4], br[2][4][4];

        // 1) load ks0 fragments (8 LDSM)
#pragma unroll
        for (int mt = 0; mt < 4; mt++)
            LDSM_X4(ar[0][mt][0], ar[0][mt][1], ar[0][mt][2], ar[0][mt][3],
                    sa + a_off + mt * (16 * ROWB));
#pragma unroll
        for (int q = 0; q < 4; q++)
            LDSM_X4(br[0][q][0], br[0][q][1], br[0][q][2], br[0][q][3],
                    sb + b_off + q * (16 * ROWB));

        // 2) issue next-stage cp.async (lands during this tile's mma)
        if (t + 3 < NT) {
            uint32_t sn = sbase + ((t + 3) & 3) * STAGE;
            int k0 = (t + 3) * BK;
#pragma unroll
            for (int l = 0; l < 4; l++) {
                int c = tid + GTHREADS * l, row = c >> 2, kc = c & 3;
                CP_ASYNC16(sn + row * ROWB + kc * 16,
                           Arow0 + (size_t)row * DIMD + k0 + kc * 8);
                CP_ASYNC16(sn + A_STG + row * ROWB + kc * 16,
                           Wrow0 + (size_t)row * DIMD + k0 + kc * 8);
            }
        }
        CP_COMMIT();

        // 3) mma ks0 first half (mt 0-1)
#pragma unroll
        for (int mt = 0; mt < 2; mt++)
#pragma unroll
            for (int nt = 0; nt < 8; nt++)
                mma_f16(acc[mt][nt], ar[0][mt],
                        br[0][nt >> 1][(nt & 1) * 2],
                        br[0][nt >> 1][(nt & 1) * 2 + 1]);

        // 4) load ks1 fragments (hidden under remaining mma)
#pragma unroll
        for (int mt = 0; mt < 4; mt++)
            LDSM_X4(ar[1][mt][0], ar[1][mt][1], ar[1][mt][2], ar[1][mt][3],
                    sa + a_off + mt * (16 * ROWB) + 32);
#pragma unroll
        for (int q = 0; q < 4; q++)
            LDSM_X4(br[1][q][0], br[1][q][1], br[1][q][2], br[1][q][3],
                    sb + b_off + q * (16 * ROWB) + 32);

        // 5) mma ks0 second half (mt 2-3)
#pragma unroll
        for (int mt = 2; mt < 4; mt++)
#pragma unroll
            for (int nt = 0; nt < 8; nt++)
                mma_f16(acc[mt][nt], ar[0][mt],
                        br[0][nt >> 1][(nt & 1) * 2],
                        br[0][nt >> 1][(nt & 1) * 2 + 1]);

        // 6) mma ks1 (all)
#pragma unroll
        for (int mt = 0; mt < 4; mt++)
#pragma unroll
            for (int nt = 0; nt < 8; nt++)
                mma_f16(acc[mt][nt], ar[1][mt],
                        br[1][nt >> 1][(nt & 1) * 2],
                        br[1][nt >> 1][(nt & 1) * 2 + 1]);
    }

    // epilogue
#pragma unroll
    for (int mt = 0; mt < 4; mt++) {
#pragma unroll
        for (int nt = 0; nt < 8; nt++) {
            int row = bm + wm * 64 + mt * 16 + g;
            int col = bn + wn * 64 + nt * 8 + t4 * 2;
            float b0 = bias[col], b1 = bias[col + 1];
            float v0 = acc[mt][nt][0] + b0;
            float v1 = acc[mt][nt][1] + b1;
            float v2 = acc[mt][nt][2] + b0;
            float v3 = acc[mt][nt][3] + b1;
            if (act) {
                v0 = (v0 > 0.0f) ? (v0 + 1.0f) : expf(v0);
                v1 = (v1 > 0.0f) ? (v1 + 1.0f) : expf(v1);
                v2 = (v2 > 0.0f) ? (v2 + 1.0f) : expf(v2);
                v3 = (v3 > 0.0f) ? (v3 + 1.0f) : expf(v3);
            }
            if (OUTH) {
                __half* C = (__half*)Cv;
                *(__half2*)&C[(size_t)row * DIMD + col]       = __floats2half2_rn(v0, v1);
                *(__half2*)&C[(size_t)(row + 8) * DIMD + col] = __floats2half2_rn(v2, v3);
            } else {
                float* C = (float*)Cv;
                *(float2*)&C[(size_t)row * DIMD + col]       = make_float2(v0, v1);
                *(float2*)&C[(size_t)(row + 8) * DIMD + col] = make_float2(v2, v3);
            }
        }
    }
}

// fused Q/K/V projection: blockIdx.z selects weight/bias/output/activation
__global__ __launch_bounds__(GTHREADS, 2)
void qkv_kernel(const __half* __restrict__ X, const __half* __restrict__ Wh,
                const float* __restrict__ bq, const float* __restrict__ bk,
                const float* __restrict__ bv,
                __half* __restrict__ Qh, __half* __restrict__ Kh,
                __half* __restrict__ Vh)
{
    extern __shared__ char smem[];
    const int z = blockIdx.z;
    const __half* W   = Wh + (size_t)z * 1048576;
    const float* bias = (z == 0) ? bq : (z == 1) ? bk : bv;
    __half* out       = (z == 0) ? Qh : (z == 1) ? Kh : Vh;
    gemm_body<1>(X, W, bias, out, z < 2 ? 1 : 0,
                 blockIdx.y * BM, blockIdx.x * BN, smem);
}

// output projection (fp32 out)
__global__ __launch_bounds__(GTHREADS, 2)
void out_kernel(const __half* __restrict__ Ah, const __half* __restrict__ Wh,
                const float* __restrict__ bo, float* __restrict__ C)
{
    extern __shared__ char smem[];
    gemm_body<0>(Ah, Wh + 3 * 1048576, bo, C, 0,
                 blockIdx.y * BM, blockIdx.x * BN, smem);
}

// ---------------- KV state via mma: atomic-free, per-chunk partials ----------
#define KV_SPLIT 8
constexpr int ROWK = 72;

__global__ __launch_bounds__(256)
void kv_mma_kernel(const __half* __restrict__ Kmat, const __half* __restrict__ Vmat,
                   float* __restrict__ KVpart, float* __restrict__ Zpart, int seq)
{
    const int bh    = blockIdx.x / KV_SPLIT;
    const int chunk = blockIdx.x % KV_SPLIT;
    const int b = bh / NH, h = bh % NH;
    const int rowsPer = seq / KV_SPLIT;
    const int n0 = chunk * rowsPer;

    const int tid  = threadIdx.x;
    const int lane = tid & 31;
    const int warp = tid >> 5;
    const int wm   = warp & 3;
    const int wn   = warp >> 2;
    const int g    = lane >> 2, t4 = lane & 3;

    __shared__ __align__(16) __half Ks[64][ROWK];
    __shared__ __align__(16) __half Vs[64][ROWK];
    __shared__ float Zred[4][64];

    const int at_r = (lane & 7) + ((lane >> 4) & 1) * 8;
    const int at_c = wm * 16 + ((lane >> 3) & 1) * 8;
    const int bt_r = (lane & 7) + ((lane >> 3) & 1) * 8;
    const int bt_cb = ((lane >> 4) & 1) * 8;

    const uint32_t ks_base = smem_u32(&Ks[0][0]);
    const uint32_t vs_base = smem_u32(&Vs[0][0]);

    float acc[4][4];
#pragma unroll
    for (int i = 0; i < 4; i++)
#pragma unroll
        for (int j = 0; j < 4; j++) acc[i][j] = 0.0f;

    const int zc = tid & 63, zr0 = (tid >> 6) * 16;
    float z = 0.0f;

    const size_t base = ((size_t)b * seq) * DIMD + h * HD;
    int srow[2], sck[2];
#pragma unroll
    for (int l = 0; l < 2; l++) {
        int c = tid + 256 * l;
        srow[l] = c >> 3; sck[l] = (c & 7) * 8;
    }

    for (int n = n0; n < n0 + rowsPer; n += 64) {
#pragma unroll
        for (int l = 0; l < 2; l++) {
            size_t gaddr = base + (size_t)(n + srow[l]) * DIMD + sck[l];
            *(uint4*)&Ks[srow[l]][sck[l]] = *(const uint4*)&Kmat[gaddr];
            *(uint4*)&Vs[srow[l]][sck[l]] = *(const uint4*)&Vmat[gaddr];
        }
        __syncthreads();

#pragma unroll
        for (int ks = 0; ks < 4; ks++) {
            uint32_t ar[4], br[2][4];
            LDSM_X4T(ar[0], ar[1], ar[2], ar[3],
                     ks_base + ((ks * 16 + at_r) * ROWK + at_c) * 2);
#pragma unroll
            for (int q = 0; q < 2; q++)
                LDSM_X4T(br[q][0], br[q][1], br[q][2], br[q][3],
                         vs_base + ((ks * 16 + bt_r) * ROWK + wn * 32 + q * 16 + bt_cb) * 2);
#pragma unroll
            for (int nt = 0; nt < 4; nt++)
                mma_f16(acc[nt], ar,
                        br[nt >> 1][(nt & 1) * 2],
                        br[nt >> 1][(nt & 1) * 2 + 1]);
        }

#pragma unroll
        for (int r = 0; r < 16; r++)
            z += __half2float(Ks[zr0 + r][zc]);
        __syncthreads();
    }

    // non-atomic partial writes
    float* kvp = KVpart + ((size_t)bh * KV_SPLIT + chunk) * 4096;
#pragma unroll
    for (int nt = 0; nt < 4; nt++) {
        int d0 = wm * 16 + g;
        int e0 = wn * 32 + nt * 8 + t4 * 2;
        kvp[d0 * HD + e0]           = acc[nt][0];
        kvp[d0 * HD + e0 + 1]       = acc[nt][1];
        kvp[(d0 + 8) * HD + e0]     = acc[nt][2];
        kvp[(d0 + 8) * HD + e0 + 1] = acc[nt][3];
    }
    Zred[tid >> 6][zc] = z;
    __syncthreads();
    if (tid < 64)
        Zpart[((size_t)bh * KV_SPLIT + chunk) * 64 + tid] =
            Zred[0][tid] + Zred[1][tid] + Zred[2][tid] + Zred[3][tid];
}

// ---------------- attn via mma (unchanged) -----------------------------------
constexpr int ROWQ = 72;

__global__ __launch_bounds__(256)
void attn_mma_kernel(const __half* __restrict__ Qmat, const __half* __restrict__ KVZ,
                     __half* __restrict__ Out, int seq)
{
    const int bh = blockIdx.x;
    const int b = bh / NH, h = bh % NH;
    const int n0 = blockIdx.y * 128;
    const int tid  = threadIdx.x;
    const int lane = tid & 31;
    const int warp = tid >> 5;
    const int g = lane >> 2, t4 = lane & 3;

    __shared__ __align__(16) __half Qs[128][ROWQ];
    __shared__ __align__(16) __half Bs[80][ROWQ];

    for (int i = tid; i < 8 * ROWQ; i += 256)
        Bs[72 + i / ROWQ][i % ROWQ] = __ushort_as_half(0);

    const __half* kvzp = KVZ + (size_t)bh * 72 * 64;
#pragma unroll
    for (int l = 0; l < 3; l++) {
        int c = tid + 256 * l;
        if (c < 576) {
            int r = c >> 3, ck = (c & 7) * 8;
            *(uint4*)&Bs[r][ck] = *(const uint4*)&kvzp[r * 64 + ck];
        }
    }

    const size_t base = ((size_t)b * seq) * DIMD + h * HD;
#pragma unroll
    for (int l = 0; l < 4; l++) {
        int c = tid + 256 * l;
        int r = c >> 3, ck = (c & 7) * 8;
        *(uint4*)&Qs[r][ck] = *(const uint4*)&Qmat[base + (size_t)(n0 + r) * DIMD + ck];
    }
    __syncthreads();

    const int a_r = (lane & 7) + ((lane >> 3) & 1) * 8;
    const int a_k = ((lane >> 4) & 1) * 8;
    const uint32_t a_off = (uint32_t)(((warp * 16 + a_r) * ROWQ + a_k) * 2);
    const int b_r = (lane & 7) + ((lane >> 4) & 1) * 8;
    const int b_k = ((lane >> 3) & 1) * 8;
    const uint32_t b_off = (uint32_t)((b_r * ROWQ + b_k) * 2);

    const uint32_t qs_base = smem_u32(&Qs[0][0]);
    const uint32_t bs_base = smem_u32(&Bs[0][0]);

    float acc[9][4];
#pragma unroll
    for (int nt = 0; nt < 9; nt++)
#pragma unroll
        for (int r = 0; r < 4; r++) acc[nt][r] = 0.0f;

#pragma unroll
    for (int ks = 0; ks < 4; ks++) {
        uint32_t ar[4], br[5][4];
        LDSM_X4(ar[0], ar[1], ar[2], ar[3], qs_base + a_off + ks * 32);
#pragma unroll
        for (int q = 0; q < 5; q++)
            LDSM_X4(br[q][0], br[q][1], br[q][2], br[q][3],
                    bs_base + b_off + q * (16 * ROWQ * 2) + ks * 32);
#pragma unroll
        for (int nt = 0; nt < 9; nt++)
            mma_f16(acc[nt], ar,
                    br[nt >> 1][(nt & 1) * 2],
                    br[nt >> 1][(nt & 1) * 2 + 1]);
    }

    float nrm0 = __shfl_sync(0xffffffffu, acc[8][0], lane & ~3);
    float nrm1 = __shfl_sync(0xffffffffu, acc[8][2], lane & ~3);
    float inv0 = 1.0f / (nrm0 + 1e-6f);
    float inv1 = 1.0f / (nrm1 + 1e-6f);

    int row0 = n0 + warp * 16 + g;
    __half* op0 = Out + base + (size_t)row0 * DIMD;
    __half* op1 = Out + base + (size_t)(row0 + 8) * DIMD;
#pragma unroll
    for (int nt = 0; nt < 8; nt++) {
        int e = nt * 8 + t4 * 2;
        *(__half2*)(op0 + e) = __floats2half2_rn(acc[nt][0] * inv0, acc[nt][1] * inv0);
        *(__half2*)(op1 + e) = __floats2half2_rn(acc[nt][2] * inv1, acc[nt][3] * inv1);
    }
}

// ---------------- launcher --------------------------------------------------
extern "C" void kernel_launch(void* const* d_in, const int* in_sizes, int n_in,
                              void* d_out, int out_size)
{
    const float* x  = (const float*)d_in[0];
    const float* Wq = (const float*)d_in[1];
    const float* bq = (const float*)d_in[2];
    const float* Wk = (const float*)d_in[3];
    const float* bk = (const float*)d_in[4];
    const float* Wv = (const float*)d_in[5];
    const float* bv = (const float*)d_in[6];
    const float* Wo = (const float*)d_in[7];
    const float* bo = (const float*)d_in[8];

    const int M   = in_sizes[0] / DIMD;   // 16384
    const int B   = 4;
    const int seq = M / B;                // 4096

    __half *Xh, *Wh, *Qh, *Kh, *Vh, *Ah, *KVZh;
    float *KVpp, *Zpp;
    cudaGetSymbolAddress((void**)&Xh,   g_Xh);
    cudaGetSymbolAddress((void**)&Wh,   g_Wh);
    cudaGetSymbolAddress((void**)&Qh,   g_Qh);
    cudaGetSymbolAddress((void**)&Kh,   g_Kh);
    cudaGetSymbolAddress((void**)&Vh,   g_Vh);
    cudaGetSymbolAddress((void**)&Ah,   g_Ah);
    cudaGetSymbolAddress((void**)&KVZh, g_KVZ);
    cudaGetSymbolAddress((void**)&KVpp, g_KVpart);
    cudaGetSymbolAddress((void**)&Zpp,  g_Zpart);

    cudaFuncSetAttribute(qkv_kernel, cudaFuncAttributeMaxDynamicSharedMemorySize, SMEM_GEMM);
    cudaFuncSetAttribute(out_kernel, cudaFuncAttributeMaxDynamicSharedMemorySize, SMEM_GEMM);

    // 0: convert inputs to fp16
    cvt_kernel<<<10485760 / 256, 256>>>(x, Wq, Wk, Wv, Wo, Xh, Wh);

    // 1: fused Q/K/V projections (phi fused into Q,K)
    qkv_kernel<<<dim3(DIMD / BN, M / BM, 3), GTHREADS, SMEM_GEMM>>>(
        Xh, Wh, bq, bk, bv, Qh, Kh, Vh);

    // 2: KV state + Z via tensor cores (atomic-free partials)
    kv_mma_kernel<<<B * NH * KV_SPLIT, 256>>>(Kh, Vh, KVpp, Zpp, seq);

    // 3: build KVZ^T fp16 (sums 8 partials)
    kvz_kernel<<<(64 * 72 * 64 + 255) / 256, 256>>>(KVpp, Zpp, KVZh);

    // 4: attention apply + normalization via tensor cores
    attn_mma_kernel<<<dim3(B * NH, seq / 128), 256>>>(Qh, KVZh, Ah, seq);

    // 5: output projection -> d_out (fp32)
    out_kernel<<<dim3(DIMD / BN, M / BM), GTHREADS, SMEM_GEMM>>>(Ah, Wh, bo, (float*)d_out);
}

// round 15
// speedup vs baseline: 1.0869x; 1.0869x over previous
#include <cuda_runtime.h>
#include <cuda_fp16.h>
#include <math.h>
#include <stdint.h>

#define DIMD 1024
#define NH   16
#define HD   64

// ---------------- scratch (device globals: no allocation allowed) ----------
__device__ __half g_Xh[16384 * 1024];          // x fp16
__device__ __half g_Wh[4 * 1024 * 1024];       // Wq|Wk|Wv|Wo fp16
__device__ __half g_Qh[16384 * 1024];          // phi(Q) fp16
__device__ __half g_Kh[16384 * 1024];          // phi(K) fp16
__device__ __half g_Vh[16384 * 1024];          // V fp16
__device__ __half g_Ah[16384 * 1024];          // attn out fp16
__device__ float  g_KVpart[64 * 8 * 64 * 64];  // [bh][chunk][e][d] fp32 (pre-transposed)
__device__ float  g_Zpart [64 * 8 * 64];       // [bh][chunk][d]
__device__ __half g_KVZ[64 * 72 * 64];         // [bh][e-row 0..71][d] fp16

// ---------------- convert inputs to fp16 ------------------------------------
__global__ void cvt_kernel(const float* __restrict__ x,
                           const float* __restrict__ wq, const float* __restrict__ wk,
                           const float* __restrict__ wv, const float* __restrict__ wo,
                           __half* __restrict__ xh, __half* __restrict__ wh)
{
    int i = blockIdx.x * blockDim.x + threadIdx.x;
    const int XP = 8388608, WP = 524288;
    if (i < XP) {
        float2 v = ((const float2*)x)[i];
        ((__half2*)xh)[i] = __floats2half2_rn(v.x, v.y);
    } else {
        int j = i - XP;
        int sel = j / WP, off = j - sel * WP;
        const float* src = (sel == 0) ? wq : (sel == 1) ? wk : (sel == 2) ? wv : wo;
        float2 v = ((const float2*)src)[off];
        ((__half2*)(wh))[sel * WP + off] = __floats2half2_rn(v.x, v.y);
    }
}

// ---------------- KVZ build: sum 8 pre-transposed partials + Z row ----------
// KVpart laid out [bh][c][e][d] -> coalesced reads (d fast across threads)
__global__ void kvz_kernel(const float* __restrict__ KVpart,
                           const float* __restrict__ Zpart,
                           __half* __restrict__ KVZ)
{
    int i = blockIdx.x * blockDim.x + threadIdx.x;   // 64*72*64
    if (i >= 64 * 72 * 64) return;
    int d  = i & 63;
    int r  = (i >> 6) % 72;
    int bh = i / (72 * 64);
    float v = 0.0f;
    if (r < 64) {
#pragma unroll
        for (int c = 0; c < 8; c++)
            v += KVpart[(((size_t)bh * 8 + c) * 64 + r) * 64 + d];
    } else if (r == 64) {
#pragma unroll
        for (int c = 0; c < 8; c++)
            v += Zpart[((size_t)bh * 8 + c) * 64 + d];
    }
    KVZ[i] = __float2half(v);
}

// ---------------- asm helpers ------------------------------------------------
__device__ __forceinline__ uint32_t smem_u32(const void* p) {
    uint32_t a;
    asm("{ .reg .u64 t; cvta.to.shared.u64 t, %1; cvt.u32.u64 %0, t; }"
        : "=r"(a) : "l"(p));
    return a;
}

#define CP_ASYNC16(dst, src) \
    asm volatile("cp.async.cg.shared.global [%0], [%1], 16;" :: "r"(dst), "l"(src))
#define CP_COMMIT() asm volatile("cp.async.commit_group;" ::: "memory")
#define CP_WAIT(n)  asm volatile("cp.async.wait_group %0;" :: "n"(n) : "memory")

#define LDSM_X4(r0, r1, r2, r3, addr) \
    asm volatile("ldmatrix.sync.aligned.m8n8.x4.shared.b16 {%0,%1,%2,%3}, [%4];" \
                 : "=r"(r0), "=r"(r1), "=r"(r2), "=r"(r3) : "r"(addr))
#define LDSM_X4T(r0, r1, r2, r3, addr) \
    asm volatile("ldmatrix.sync.aligned.m8n8.x4.trans.shared.b16 {%0,%1,%2,%3}, [%4];" \
                 : "=r"(r0), "=r"(r1), "=r"(r2), "=r"(r3) : "r"(addr))

__device__ __forceinline__ void mma_f16(float* d, const uint32_t* a,
                                        uint32_t b0, uint32_t b1) {
    asm volatile(
        "mma.sync.aligned.m16n8k16.row.col.f32.f16.f16.f32 "
        "{%0,%1,%2,%3}, {%4,%5,%6,%7}, {%8,%9}, {%0,%1,%2,%3};"
        : "+f"(d[0]), "+f"(d[1]), "+f"(d[2]), "+f"(d[3])
        : "r"(a[0]), "r"(a[1]), "r"(a[2]), "r"(a[3]), "r"(b0), "r"(b1));
}

// ---------------- fp16 GEMM: 128x128x32 CTA, 4 warps, 64x64 warp tile -------
// R11 body verbatim: front-loaded LDSM block, cp.async under mma, ks-outer mma.
constexpr int BM = 128, BN = 128, BK = 32;
constexpr int ROWB   = 80;                       // 64B data + 16B pad per row
constexpr int A_STG  = BM * ROWB;                // 10240 B
constexpr int STAGE  = 2 * A_STG;                // 20480 B
constexpr int NSTAGE = 4;
constexpr int SMEM_GEMM = NSTAGE * STAGE;        // 81920 B
constexpr int GTHREADS  = 128;

template <int OUTH>
__device__ __forceinline__
void gemm_body(const __half* __restrict__ A, const __half* __restrict__ W,
               const float* __restrict__ bias, void* __restrict__ Cv,
               int act, int bm, int bn, char* smem)
{
    const uint32_t sbase = smem_u32(smem);
    const int tid  = threadIdx.x;
    const int lane = tid & 31;
    const int warp = tid >> 5;     // 0..3
    const int wm   = warp & 1;     // 64-row slab
    const int wn   = warp >> 1;    // 64-col slab
    const int g    = lane >> 2, t4 = lane & 3;

    const __half* Arow0 = A + (size_t)bm * DIMD;
    const __half* Wrow0 = W + (size_t)bn * DIMD;

    const int a_r = (lane & 7) + ((lane >> 3) & 1) * 8;
    const int a_k = ((lane >> 4) & 1) * 8;
    const uint32_t a_off = (uint32_t)((wm * 64 + a_r) * ROWB + a_k * 2);
    const int b_r = (lane & 7) + ((lane >> 4) & 1) * 8;
    const int b_k = ((lane >> 3) & 1) * 8;
    const uint32_t b_off = (uint32_t)((wn * 64 + b_r) * ROWB + b_k * 2);

    float acc[4][8][4];
#pragma unroll
    for (int mt = 0; mt < 4; mt++)
#pragma unroll
        for (int nt = 0; nt < 8; nt++)
#pragma unroll
            for (int r = 0; r < 4; r++) acc[mt][nt][r] = 0.0f;

    const int NT = DIMD / BK;   // 32

    // staging: 512 chunks per operand, 128 threads -> 4 each
#pragma unroll
    for (int t = 0; t < 3; t++) {
        uint32_t sa = sbase + t * STAGE;
#pragma unroll
        for (int l = 0; l < 4; l++) {
            int c = tid + GTHREADS * l, row = c >> 2, kc = c & 3;
            CP_ASYNC16(sa + row * ROWB + kc * 16,
                       Arow0 + (size_t)row * DIMD + t * BK + kc * 8);
            CP_ASYNC16(sa + A_STG + row * ROWB + kc * 16,
                       Wrow0 + (size_t)row * DIMD + t * BK + kc * 8);
        }
        CP_COMMIT();
    }

    for (int t = 0; t < NT; t++) {
        CP_WAIT(2);
        __syncthreads();

        const uint32_t sa = sbase + (t & 3) * STAGE;
        const uint32_t sb = sa + A_STG;

        // 1) front-load ALL fragments for this k-tile (both ks halves)
        uint32_t ar[2][4][4], br[2][4][4];
#pragma unroll
        for (int ks = 0; ks < 2; ks++) {
#pragma unroll
            for (int mt = 0; mt < 4; mt++)
                LDSM_X4(ar[ks][mt][0], ar[ks][mt][1], ar[ks][mt][2], ar[ks][mt][3],
                        sa + a_off + mt * (16 * ROWB) + ks * 32);
#pragma unroll
            for (int q = 0; q < 4; q++)
                LDSM_X4(br[ks][q][0], br[ks][q][1], br[ks][q][2], br[ks][q][3],
                        sb + b_off + q * (16 * ROWB) + ks * 32);
        }

        // 2) issue next-stage cp.async (lands during the mma block)
        if (t + 3 < NT) {
            uint32_t sn = sbase + ((t + 3) & 3) * STAGE;
            int k0 = (t + 3) * BK;
#pragma unroll
            for (int l = 0; l < 4; l++) {
                int c = tid + GTHREADS * l, row = c >> 2, kc = c & 3;
                CP_ASYNC16(sn + row * ROWB + kc * 16,
                           Arow0 + (size_t)row * DIMD + k0 + kc * 8);
                CP_ASYNC16(sn + A_STG + row * ROWB + kc * 16,
                           Wrow0 + (size_t)row * DIMD + k0 + kc * 8);
            }
        }
        CP_COMMIT();

        // 3) 64 mma, ks-outer: consecutive mma never share an accumulator
#pragma unroll
        for (int ks = 0; ks < 2; ks++)
#pragma unroll
            for (int mt = 0; mt < 4; mt++)
#pragma unroll
                for (int nt = 0; nt < 8; nt++)
                    mma_f16(acc[mt][nt], ar[ks][mt],
                            br[ks][nt >> 1][(nt & 1) * 2],
                            br[ks][nt >> 1][(nt & 1) * 2 + 1]);
    }

    // epilogue
#pragma unroll
    for (int mt = 0; mt < 4; mt++) {
#pragma unroll
        for (int nt = 0; nt < 8; nt++) {
            int row = bm + wm * 64 + mt * 16 + g;
            int col = bn + wn * 64 + nt * 8 + t4 * 2;
            float b0 = bias[col], b1 = bias[col + 1];
            float v0 = acc[mt][nt][0] + b0;
            float v1 = acc[mt][nt][1] + b1;
            float v2 = acc[mt][nt][2] + b0;
            float v3 = acc[mt][nt][3] + b1;
            if (act) {
                v0 = (v0 > 0.0f) ? (v0 + 1.0f) : expf(v0);
                v1 = (v1 > 0.0f) ? (v1 + 1.0f) : expf(v1);
                v2 = (v2 > 0.0f) ? (v2 + 1.0f) : expf(v2);
                v3 = (v3 > 0.0f) ? (v3 + 1.0f) : expf(v3);
            }
            if (OUTH) {
                __half* C = (__half*)Cv;
                *(__half2*)&C[(size_t)row * DIMD + col]       = __floats2half2_rn(v0, v1);
                *(__half2*)&C[(size_t)(row + 8) * DIMD + col] = __floats2half2_rn(v2, v3);
            } else {
                float* C = (float*)Cv;
                *(float2*)&C[(size_t)row * DIMD + col]       = make_float2(v0, v1);
                *(float2*)&C[(size_t)(row + 8) * DIMD + col] = make_float2(v2, v3);
            }
        }
    }
}

// fused Q/K/V projection: blockIdx.z selects weight/bias/output/activation
__global__ __launch_bounds__(GTHREADS, 2)
void qkv_kernel(const __half* __restrict__ X, const __half* __restrict__ Wh,
                const float* __restrict__ bq, const float* __restrict__ bk,
                const float* __restrict__ bv,
                __half* __restrict__ Qh, __half* __restrict__ Kh,
                __half* __restrict__ Vh)
{
    extern __shared__ char smem[];
    const int z = blockIdx.z;
    const __half* W   = Wh + (size_t)z * 1048576;
    const float* bias = (z == 0) ? bq : (z == 1) ? bk : bv;
    __half* out       = (z == 0) ? Qh : (z == 1) ? Kh : Vh;
    gemm_body<1>(X, W, bias, out, z < 2 ? 1 : 0,
                 blockIdx.y * BM, blockIdx.x * BN, smem);
}

// output projection (fp32 out)
__global__ __launch_bounds__(GTHREADS, 2)
void out_kernel(const __half* __restrict__ Ah, const __half* __restrict__ Wh,
                const float* __restrict__ bo, float* __restrict__ C)
{
    extern __shared__ char smem[];
    gemm_body<0>(Ah, Wh + 3 * 1048576, bo, C, 0,
                 blockIdx.y * BM, blockIdx.x * BN, smem);
}

// ---------------- KV state via mma: atomic-free, pre-transposed partials ----
#define KV_SPLIT 8
constexpr int ROWK = 72;

__global__ __launch_bounds__(256)
void kv_mma_kernel(const __half* __restrict__ Kmat, const __half* __restrict__ Vmat,
                   float* __restrict__ KVpart, float* __restrict__ Zpart, int seq)
{
    const int bh    = blockIdx.x / KV_SPLIT;
    const int chunk = blockIdx.x % KV_SPLIT;
    const int b = bh / NH, h = bh % NH;
    const int rowsPer = seq / KV_SPLIT;
    const int n0 = chunk * rowsPer;

    const int tid  = threadIdx.x;
    const int lane = tid & 31;
    const int warp = tid >> 5;
    const int wm   = warp & 3;
    const int wn   = warp >> 2;
    const int g    = lane >> 2, t4 = lane & 3;

    __shared__ __align__(16) __half Ks[64][ROWK];
    __shared__ __align__(16) __half Vs[64][ROWK];
    __shared__ float Zred[4][64];

    const int at_r = (lane & 7) + ((lane >> 4) & 1) * 8;
    const int at_c = wm * 16 + ((lane >> 3) & 1) * 8;
    const int bt_r = (lane & 7) + ((lane >> 3) & 1) * 8;
    const int bt_cb = ((lane >> 4) & 1) * 8;

    const uint32_t ks_base = smem_u32(&Ks[0][0]);
    const uint32_t vs_base = smem_u32(&Vs[0][0]);

    float acc[4][4];
#pragma unroll
    for (int i = 0; i < 4; i++)
#pragma unroll
        for (int j = 0; j < 4; j++) acc[i][j] = 0.0f;

    const int zc = tid & 63, zr0 = (tid >> 6) * 16;
    float z = 0.0f;

    const size_t base = ((size_t)b * seq) * DIMD + h * HD;
    int srow[2], sck[2];
#pragma unroll
    for (int l = 0; l < 2; l++) {
        int c = tid + 256 * l;
        srow[l] = c >> 3; sck[l] = (c & 7) * 8;
    }

    for (int n = n0; n < n0 + rowsPer; n += 64) {
#pragma unroll
        for (int l = 0; l < 2; l++) {
            size_t gaddr = base + (size_t)(n + srow[l]) * DIMD + sck[l];
            *(uint4*)&Ks[srow[l]][sck[l]] = *(const uint4*)&Kmat[gaddr];
            *(uint4*)&Vs[srow[l]][sck[l]] = *(const uint4*)&Vmat[gaddr];
        }
        __syncthreads();

#pragma unroll
        for (int ks = 0; ks < 4; ks++) {
            uint32_t ar[4], br[2][4];
            LDSM_X4T(ar[0], ar[1], ar[2], ar[3],
                     ks_base + ((ks * 16 + at_r) * ROWK + at_c) * 2);
#pragma unroll
            for (int q = 0; q < 2; q++)
                LDSM_X4T(br[q][0], br[q][1], br[q][2], br[q][3],
                         vs_base + ((ks * 16 + bt_r) * ROWK + wn * 32 + q * 16 + bt_cb) * 2);
#pragma unroll
            for (int nt = 0; nt < 4; nt++)
                mma_f16(acc[nt], ar,
                        br[nt >> 1][(nt & 1) * 2],
                        br[nt >> 1][(nt & 1) * 2 + 1]);
        }

#pragma unroll
        for (int r = 0; r < 16; r++)
            z += __half2float(Ks[zr0 + r][zc]);
        __syncthreads();
    }

    // non-atomic partial writes, TRANSPOSED layout [e][d]
    float* kvp = KVpart + ((size_t)bh * KV_SPLIT + chunk) * 4096;
#pragma unroll
    for (int nt = 0; nt < 4; nt++) {
        int d0 = wm * 16 + g;
        int e0 = wn * 32 + nt * 8 + t4 * 2;
        kvp[e0 * HD + d0]           = acc[nt][0];
        kvp[(e0 + 1) * HD + d0]     = acc[nt][1];
        kvp[e0 * HD + d0 + 8]       = acc[nt][2];
        kvp[(e0 + 1) * HD + d0 + 8] = acc[nt][3];
    }
    Zred[tid >> 6][zc] = z;
    __syncthreads();
    if (tid < 64)
        Zpart[((size_t)bh * KV_SPLIT + chunk) * 64 + tid] =
            Zred[0][tid] + Zred[1][tid] + Zred[2][tid] + Zred[3][tid];
}

// ---------------- attn via mma (unchanged) -----------------------------------
constexpr int ROWQ = 72;

__global__ __launch_bounds__(256)
void attn_mma_kernel(const __half* __restrict__ Qmat, const __half* __restrict__ KVZ,
                     __half* __restrict__ Out, int seq)
{
    const int bh = blockIdx.x;
    const int b = bh / NH, h = bh % NH;
    const int n0 = blockIdx.y * 128;
    const int tid  = threadIdx.x;
    const int lane = tid & 31;
    const int warp = tid >> 5;
    const int g = lane >> 2, t4 = lane & 3;

    __shared__ __align__(16) __half Qs[128][ROWQ];
    __shared__ __align__(16) __half Bs[80][ROWQ];

    for (int i = tid; i < 8 * ROWQ; i += 256)
        Bs[72 + i / ROWQ][i % ROWQ] = __ushort_as_half(0);

    const __half* kvzp = KVZ + (size_t)bh * 72 * 64;
#pragma unroll
    for (int l = 0; l < 3; l++) {
        int c = tid + 256 * l;
        if (c < 576) {
            int r = c >> 3, ck = (c & 7) * 8;
            *(uint4*)&Bs[r][ck] = *(const uint4*)&kvzp[r * 64 + ck];
        }
    }

    const size_t base = ((size_t)b * seq) * DIMD + h * HD;
#pragma unroll
    for (int l = 0; l < 4; l++) {
        int c = tid + 256 * l;
        int r = c >> 3, ck = (c & 7) * 8;
        *(uint4*)&Qs[r][ck] = *(const uint4*)&Qmat[base + (size_t)(n0 + r) * DIMD + ck];
    }
    __syncthreads();

    const int a_r = (lane & 7) + ((lane >> 3) & 1) * 8;
    const int a_k = ((lane >> 4) & 1) * 8;
    const uint32_t a_off = (uint32_t)(((warp * 16 + a_r) * ROWQ + a_k) * 2);
    const int b_r = (lane & 7) + ((lane >> 4) & 1) * 8;
    const int b_k = ((lane >> 3) & 1) * 8;
    const uint32_t b_off = (uint32_t)((b_r * ROWQ + b_k) * 2);

    const uint32_t qs_base = smem_u32(&Qs[0][0]);
    const uint32_t bs_base = smem_u32(&Bs[0][0]);

    float acc[9][4];
#pragma unroll
    for (int nt = 0; nt < 9; nt++)
#pragma unroll
        for (int r = 0; r < 4; r++) acc[nt][r] = 0.0f;

#pragma unroll
    for (int ks = 0; ks < 4; ks++) {
        uint32_t ar[4], br[5][4];
        LDSM_X4(ar[0], ar[1], ar[2], ar[3], qs_base + a_off + ks * 32);
#pragma unroll
        for (int q = 0; q < 5; q++)
            LDSM_X4(br[q][0], br[q][1], br[q][2], br[q][3],
                    bs_base + b_off + q * (16 * ROWQ * 2) + ks * 32);
#pragma unroll
        for (int nt = 0; nt < 9; nt++)
            mma_f16(acc[nt], ar,
                    br[nt >> 1][(nt & 1) * 2],
                    br[nt >> 1][(nt & 1) * 2 + 1]);
    }

    float nrm0 = __shfl_sync(0xffffffffu, acc[8][0], lane & ~3);
    float nrm1 = __shfl_sync(0xffffffffu, acc[8][2], lane & ~3);
    float inv0 = 1.0f / (nrm0 + 1e-6f);
    float inv1 = 1.0f / (nrm1 + 1e-6f);

    int row0 = n0 + warp * 16 + g;
    __half* op0 = Out + base + (size_t)row0 * DIMD;
    __half* op1 = Out + base + (size_t)(row0 + 8) * DIMD;
#pragma unroll
    for (int nt = 0; nt < 8; nt++) {
        int e = nt * 8 + t4 * 2;
        *(__half2*)(op0 + e) = __floats2half2_rn(acc[nt][0] * inv0, acc[nt][1] * inv0);
        *(__half2*)(op1 + e) = __floats2half2_rn(acc[nt][2] * inv1, acc[nt][3] * inv1);
    }
}

// ---------------- launcher --------------------------------------------------
extern "C" void kernel_launch(void* const* d_in, const int* in_sizes, int n_in,
                              void* d_out, int out_size)
{
    const float* x  = (const float*)d_in[0];
    const float* Wq = (const float*)d_in[1];
    const float* bq = (const float*)d_in[2];
    const float* Wk = (const float*)d_in[3];
    const float* bk = (const float*)d_in[4];
    const float* Wv = (const float*)d_in[5];
    const float* bv = (const float*)d_in[6];
    const float* Wo = (const float*)d_in[7];
    const float* bo = (const float*)d_in[8];

    const int M   = in_sizes[0] / DIMD;   // 16384
    const int B   = 4;
    const int seq = M / B;                // 4096

    __half *Xh, *Wh, *Qh, *Kh, *Vh, *Ah, *KVZh;
    float *KVpp, *Zpp;
    cudaGetSymbolAddress((void**)&Xh,   g_Xh);
    cudaGetSymbolAddress((void**)&Wh,   g_Wh);
    cudaGetSymbolAddress((void**)&Qh,   g_Qh);
    cudaGetSymbolAddress((void**)&Kh,   g_Kh);
    cudaGetSymbolAddress((void**)&Vh,   g_Vh);
    cudaGetSymbolAddress((void**)&Ah,   g_Ah);
    cudaGetSymbolAddress((void**)&KVZh, g_KVZ);
    cudaGetSymbolAddress((void**)&KVpp, g_KVpart);
    cudaGetSymbolAddress((void**)&Zpp,  g_Zpart);

    cudaFuncSetAttribute(qkv_kernel, cudaFuncAttributeMaxDynamicSharedMemorySize, SMEM_GEMM);
    cudaFuncSetAttribute(out_kernel, cudaFuncAttributeMaxDynamicSharedMemorySize, SMEM_GEMM);

    // 0: convert inputs to fp16
    cvt_kernel<<<10485760 / 256, 256>>>(x, Wq, Wk, Wv, Wo, Xh, Wh);

    // 1: fused Q/K/V projections (phi fused into Q,K)
    qkv_kernel<<<dim3(DIMD / BN, M / BM, 3), GTHREADS, SMEM_GEMM>>>(
        Xh, Wh, bq, bk, bv, Qh, Kh, Vh);

    // 2: KV state + Z via tensor cores (atomic-free, pre-transposed partials)
    kv_mma_kernel<<<B * NH * KV_SPLIT, 256>>>(Kh, Vh, KVpp, Zpp, seq);

    // 3: build KVZ fp16 (coalesced partial reduction)
    kvz_kernel<<<(64 * 72 * 64 + 255) / 256, 256>>>(KVpp, Zpp, KVZh);

    // 4: attention apply + normalization via tensor cores
    attn_mma_kernel<<<dim3(B * NH, seq / 128), 256>>>(Qh, KVZh, Ah, seq);

    // 5: output projection -> d_out (fp32)
    out_kernel<<<dim3(DIMD / BN, M / BM), GTHREADS, SMEM_GEMM>>>(Ah, Wh, bo, (float*)d_out);
}

// round 16
// speedup vs baseline: 1.1133x; 1.0242x over previous
#include <cuda_runtime.h>
#include <cuda_fp16.h>
#include <math.h>
#include <stdint.h>

#define DIMD 1024
#define NH   16
#define HD   64

// ---------------- scratch (device globals: no allocation allowed) ----------
__device__ __half g_Xh[16384 * 1024];          // x fp16
__device__ __half g_Wh[4 * 1024 * 1024];       // Wq|Wk|Wv|Wo fp16
__device__ __half g_Qh[16384 * 1024];          // phi(Q) fp16
__device__ __half g_Kh[16384 * 1024];          // phi(K) fp16
__device__ __half g_Vh[16384 * 1024];          // V fp16
__device__ __half g_Ah[16384 * 1024];          // attn out fp16
__device__ float  g_KVpart[64 * 8 * 64 * 64];  // [bh][chunk][e][d] fp32 (pre-transposed)
__device__ float  g_Zpart [64 * 8 * 64];       // [bh][chunk][d]
__device__ __half g_KVZ[64 * 72 * 64];         // [bh][e-row 0..71][d] fp16

// ---------------- convert inputs to fp16 (float4-wide) -----------------------
// x: 4194304 float4s, each W: 262144 float4s -> 5242880 threads total
__global__ void cvt_kernel(const float* __restrict__ x,
                           const float* __restrict__ wq, const float* __restrict__ wk,
                           const float* __restrict__ wv, const float* __restrict__ wo,
                           __half* __restrict__ xh, __half* __restrict__ wh)
{
    int i = blockIdx.x * blockDim.x + threadIdx.x;
    const int XF4 = 4194304, WF4 = 262144;
    if (i < XF4) {
        float4 v = ((const float4*)x)[i];
        ((__half2*)xh)[2 * i]     = __floats2half2_rn(v.x, v.y);
        ((__half2*)xh)[2 * i + 1] = __floats2half2_rn(v.z, v.w);
    } else {
        int j = i - XF4;
        int sel = j / WF4, off = j - sel * WF4;
        const float* src = (sel == 0) ? wq : (sel == 1) ? wk : (sel == 2) ? wv : wo;
        float4 v = ((const float4*)src)[off];
        int o = sel * WF4 + off;
        ((__half2*)wh)[2 * o]     = __floats2half2_rn(v.x, v.y);
        ((__half2*)wh)[2 * o + 1] = __floats2half2_rn(v.z, v.w);
    }
}

// ---------------- KVZ build: sum 8 pre-transposed partials + Z row ----------
__global__ void kvz_kernel(const float* __restrict__ KVpart,
                           const float* __restrict__ Zpart,
                           __half* __restrict__ KVZ)
{
    int i = blockIdx.x * blockDim.x + threadIdx.x;   // 64*72*64
    if (i >= 64 * 72 * 64) return;
    int d  = i & 63;
    int r  = (i >> 6) % 72;
    int bh = i / (72 * 64);
    float v = 0.0f;
    if (r < 64) {
#pragma unroll
        for (int c = 0; c < 8; c++)
            v += KVpart[(((size_t)bh * 8 + c) * 64 + r) * 64 + d];
    } else if (r == 64) {
#pragma unroll
        for (int c = 0; c < 8; c++)
            v += Zpart[((size_t)bh * 8 + c) * 64 + d];
    }
    KVZ[i] = __float2half(v);
}

// ---------------- asm helpers ------------------------------------------------
__device__ __forceinline__ uint32_t smem_u32(const void* p) {
    uint32_t a;
    asm("{ .reg .u64 t; cvta.to.shared.u64 t, %1; cvt.u32.u64 %0, t; }"
        : "=r"(a) : "l"(p));
    return a;
}

#define CP_ASYNC16(dst, src) \
    asm volatile("cp.async.cg.shared.global [%0], [%1], 16;" :: "r"(dst), "l"(src))
#define CP_COMMIT() asm volatile("cp.async.commit_group;" ::: "memory")
#define CP_WAIT(n)  asm volatile("cp.async.wait_group %0;" :: "n"(n) : "memory")

#define LDSM_X4(r0, r1, r2, r3, addr) \
    asm volatile("ldmatrix.sync.aligned.m8n8.x4.shared.b16 {%0,%1,%2,%3}, [%4];" \
                 : "=r"(r0), "=r"(r1), "=r"(r2), "=r"(r3) : "r"(addr))
#define LDSM_X4T(r0, r1, r2, r3, addr) \
    asm volatile("ldmatrix.sync.aligned.m8n8.x4.trans.shared.b16 {%0,%1,%2,%3}, [%4];" \
                 : "=r"(r0), "=r"(r1), "=r"(r2), "=r"(r3) : "r"(addr))

__device__ __forceinline__ void mma_f16(float* d, const uint32_t* a,
                                        uint32_t b0, uint32_t b1) {
    asm volatile(
        "mma.sync.aligned.m16n8k16.row.col.f32.f16.f16.f32 "
        "{%0,%1,%2,%3}, {%4,%5,%6,%7}, {%8,%9}, {%0,%1,%2,%3};"
        : "+f"(d[0]), "+f"(d[1]), "+f"(d[2]), "+f"(d[3])
        : "r"(a[0]), "r"(a[1]), "r"(a[2]), "r"(a[3]), "r"(b0), "r"(b1));
}

// ---------------- fp16 GEMM: 128x128x32 CTA, 4 warps, 64x64 warp tile -------
// R11 body verbatim (best known): front-loaded LDSM block, cp.async under mma.
constexpr int BM = 128, BN = 128, BK = 32;
constexpr int ROWB   = 80;
constexpr int A_STG  = BM * ROWB;
constexpr int STAGE  = 2 * A_STG;
constexpr int NSTAGE = 4;
constexpr int SMEM_GEMM = NSTAGE * STAGE;
constexpr int GTHREADS  = 128;

template <int OUTH>
__device__ __forceinline__
void gemm_body(const __half* __restrict__ A, const __half* __restrict__ W,
               const float* __restrict__ bias, void* __restrict__ Cv,
               int act, int bm, int bn, char* smem)
{
    const uint32_t sbase = smem_u32(smem);
    const int tid  = threadIdx.x;
    const int lane = tid & 31;
    const int warp = tid >> 5;
    const int wm   = warp & 1;
    const int wn   = warp >> 1;
    const int g    = lane >> 2, t4 = lane & 3;

    const __half* Arow0 = A + (size_t)bm * DIMD;
    const __half* Wrow0 = W + (size_t)bn * DIMD;

    const int a_r = (lane & 7) + ((lane >> 3) & 1) * 8;
    const int a_k = ((lane >> 4) & 1) * 8;
    const uint32_t a_off = (uint32_t)((wm * 64 + a_r) * ROWB + a_k * 2);
    const int b_r = (lane & 7) + ((lane >> 4) & 1) * 8;
    const int b_k = ((lane >> 3) & 1) * 8;
    const uint32_t b_off = (uint32_t)((wn * 64 + b_r) * ROWB + b_k * 2);

    float acc[4][8][4];
#pragma unroll
    for (int mt = 0; mt < 4; mt++)
#pragma unroll
        for (int nt = 0; nt < 8; nt++)
#pragma unroll
            for (int r = 0; r < 4; r++) acc[mt][nt][r] = 0.0f;

    const int NT = DIMD / BK;   // 32

#pragma unroll
    for (int t = 0; t < 3; t++) {
        uint32_t sa = sbase + t * STAGE;
#pragma unroll
        for (int l = 0; l < 4; l++) {
            int c = tid + GTHREADS * l, row = c >> 2, kc = c & 3;
            CP_ASYNC16(sa + row * ROWB + kc * 16,
                       Arow0 + (size_t)row * DIMD + t * BK + kc * 8);
            CP_ASYNC16(sa + A_STG + row * ROWB + kc * 16,
                       Wrow0 + (size_t)row * DIMD + t * BK + kc * 8);
        }
        CP_COMMIT();
    }

    for (int t = 0; t < NT; t++) {
        CP_WAIT(2);
        __syncthreads();

        const uint32_t sa = sbase + (t & 3) * STAGE;
        const uint32_t sb = sa + A_STG;

        uint32_t ar[2][4][4], br[2][4][4];
#pragma unroll
        for (int ks = 0; ks < 2; ks++) {
#pragma unroll
            for (int mt = 0; mt < 4; mt++)
                LDSM_X4(ar[ks][mt][0], ar[ks][mt][1], ar[ks][mt][2], ar[ks][mt][3],
                        sa + a_off + mt * (16 * ROWB) + ks * 32);
#pragma unroll
            for (int q = 0; q < 4; q++)
                LDSM_X4(br[ks][q][0], br[ks][q][1], br[ks][q][2], br[ks][q][3],
                        sb + b_off + q * (16 * ROWB) + ks * 32);
        }

        if (t + 3 < NT) {
            uint32_t sn = sbase + ((t + 3) & 3) * STAGE;
            int k0 = (t + 3) * BK;
#pragma unroll
            for (int l = 0; l < 4; l++) {
                int c = tid + GTHREADS * l, row = c >> 2, kc = c & 3;
                CP_ASYNC16(sn + row * ROWB + kc * 16,
                           Arow0 + (size_t)row * DIMD + k0 + kc * 8);
                CP_ASYNC16(sn + A_STG + row * ROWB + kc * 16,
                           Wrow0 + (size_t)row * DIMD + k0 + kc * 8);
            }
        }
        CP_COMMIT();

#pragma unroll
        for (int ks = 0; ks < 2; ks++)
#pragma unroll
            for (int mt = 0; mt < 4; mt++)
#pragma unroll
                for (int nt = 0; nt < 8; nt++)
                    mma_f16(acc[mt][nt], ar[ks][mt],
                            br[ks][nt >> 1][(nt & 1) * 2],
                            br[ks][nt >> 1][(nt & 1) * 2 + 1]);
    }

#pragma unroll
    for (int mt = 0; mt < 4; mt++) {
#pragma unroll
        for (int nt = 0; nt < 8; nt++) {
            int row = bm + wm * 64 + mt * 16 + g;
            int col = bn + wn * 64 + nt * 8 + t4 * 2;
            float b0 = bias[col], b1 = bias[col + 1];
            float v0 = acc[mt][nt][0] + b0;
            float v1 = acc[mt][nt][1] + b1;
            float v2 = acc[mt][nt][2] + b0;
            float v3 = acc[mt][nt][3] + b1;
            if (act) {
                v0 = (v0 > 0.0f) ? (v0 + 1.0f) : expf(v0);
                v1 = (v1 > 0.0f) ? (v1 + 1.0f) : expf(v1);
                v2 = (v2 > 0.0f) ? (v2 + 1.0f) : expf(v2);
                v3 = (v3 > 0.0f) ? (v3 + 1.0f) : expf(v3);
            }
            if (OUTH) {
                __half* C = (__half*)Cv;
                *(__half2*)&C[(size_t)row * DIMD + col]       = __floats2half2_rn(v0, v1);
                *(__half2*)&C[(size_t)(row + 8) * DIMD + col] = __floats2half2_rn(v2, v3);
            } else {
                float* C = (float*)Cv;
                *(float2*)&C[(size_t)row * DIMD + col]       = make_float2(v0, v1);
                *(float2*)&C[(size_t)(row + 8) * DIMD + col] = make_float2(v2, v3);
            }
        }
    }
}

__global__ __launch_bounds__(GTHREADS, 2)
void qkv_kernel(const __half* __restrict__ X, const __half* __restrict__ Wh,
                const float* __restrict__ bq, const float* __restrict__ bk,
                const float* __restrict__ bv,
                __half* __restrict__ Qh, __half* __restrict__ Kh,
                __half* __restrict__ Vh)
{
    extern __shared__ char smem[];
    const int z = blockIdx.z;
    const __half* W   = Wh + (size_t)z * 1048576;
    const float* bias = (z == 0) ? bq : (z == 1) ? bk : bv;
    __half* out       = (z == 0) ? Qh : (z == 1) ? Kh : Vh;
    gemm_body<1>(X, W, bias, out, z < 2 ? 1 : 0,
                 blockIdx.y * BM, blockIdx.x * BN, smem);
}

__global__ __launch_bounds__(GTHREADS, 2)
void out_kernel(const __half* __restrict__ Ah, const __half* __restrict__ Wh,
                const float* __restrict__ bo, float* __restrict__ C)
{
    extern __shared__ char smem[];
    gemm_body<0>(Ah, Wh + 3 * 1048576, bo, C, 0,
                 blockIdx.y * BM, blockIdx.x * BN, smem);
}

// ---------------- KV state via mma: cp.async double-buffered ----------------
#define KV_SPLIT 8
constexpr int ROWK = 72;
constexpr int KVBUF = 64 * ROWK * 2;   // 9216 B per stage per matrix

__global__ __launch_bounds__(256)
void kv_mma_kernel(const __half* __restrict__ Kmat, const __half* __restrict__ Vmat,
                   float* __restrict__ KVpart, float* __restrict__ Zpart, int seq)
{
    const int bh    = blockIdx.x / KV_SPLIT;
    const int chunk = blockIdx.x % KV_SPLIT;
    const int b = bh / NH, h = bh % NH;
    const int rowsPer = seq / KV_SPLIT;     // 512
    const int n0 = chunk * rowsPer;

    const int tid  = threadIdx.x;
    const int lane = tid & 31;
    const int warp = tid >> 5;
    const int wm   = warp & 3;
    const int wn   = warp >> 2;
    const int g    = lane >> 2, t4 = lane & 3;

    __shared__ __align__(16) __half Ks[2][64][ROWK];
    __shared__ __align__(16) __half Vs[2][64][ROWK];
    __shared__ float Zred[4][64];

    const int at_r = (lane & 7) + ((lane >> 4) & 1) * 8;
    const int at_c = wm * 16 + ((lane >> 3) & 1) * 8;
    const int bt_r = (lane & 7) + ((lane >> 3) & 1) * 8;
    const int bt_cb = ((lane >> 4) & 1) * 8;

    const uint32_t ks_base = smem_u32(&Ks[0][0][0]);
    const uint32_t vs_base = smem_u32(&Vs[0][0][0]);

    float acc[4][4];
#pragma unroll
    for (int i = 0; i < 4; i++)
#pragma unroll
        for (int j = 0; j < 4; j++) acc[i][j] = 0.0f;

    const int zc = tid & 63, zr0 = (tid >> 6) * 16;
    float z = 0.0f;

    const size_t base = ((size_t)b * seq) * DIMD + h * HD;
    // staging: 512 16B chunks per matrix, 256 threads -> 2 each
    int srow[2], sck[2];
#pragma unroll
    for (int l = 0; l < 2; l++) {
        int c = tid + 256 * l;
        srow[l] = c >> 3; sck[l] = (c & 7) * 8;
    }

    // prologue: stage tile 0 into buffer 0
#pragma unroll
    for (int l = 0; l < 2; l++) {
        size_t gaddr = base + (size_t)(n0 + srow[l]) * DIMD + sck[l];
        uint32_t soff = srow[l] * (ROWK * 2) + sck[l] * 2;
        CP_ASYNC16(ks_base + soff, Kmat + gaddr);
        CP_ASYNC16(vs_base + soff, Vmat + gaddr);
    }
    CP_COMMIT();

    const int NITER = rowsPer / 64;   // 8
    for (int it = 0; it < NITER; it++) {
        const int cur = it & 1, nxt = cur ^ 1;

        __syncthreads();   // prev compute done with nxt buffer

        // issue next tile into nxt (empty commit on last iter keeps counts uniform)
        if (it + 1 < NITER) {
            int n = n0 + (it + 1) * 64;
#pragma unroll
            for (int l = 0; l < 2; l++) {
                size_t gaddr = base + (size_t)(n + srow[l]) * DIMD + sck[l];
                uint32_t soff = nxt * KVBUF + srow[l] * (ROWK * 2) + sck[l] * 2;
                CP_ASYNC16(ks_base + soff, Kmat + gaddr);
                CP_ASYNC16(vs_base + soff, Vmat + gaddr);
            }
        }
        CP_COMMIT();

        CP_WAIT(1);        // current tile arrived
        __syncthreads();

        const uint32_t kb = ks_base + cur * KVBUF;
        const uint32_t vb = vs_base + cur * KVBUF;
#pragma unroll
        for (int ks = 0; ks < 4; ks++) {
            uint32_t ar[4], br[2][4];
            LDSM_X4T(ar[0], ar[1], ar[2], ar[3],
                     kb + ((ks * 16 + at_r) * ROWK + at_c) * 2);
#pragma unroll
            for (int q = 0; q < 2; q++)
                LDSM_X4T(br[q][0], br[q][1], br[q][2], br[q][3],
                         vb + ((ks * 16 + bt_r) * ROWK + wn * 32 + q * 16 + bt_cb) * 2);
#pragma unroll
            for (int nt = 0; nt < 4; nt++)
                mma_f16(acc[nt], ar,
                        br[nt >> 1][(nt & 1) * 2],
                        br[nt >> 1][(nt & 1) * 2 + 1]);
        }

#pragma unroll
        for (int r = 0; r < 16; r++)
            z += __half2float(Ks[cur][zr0 + r][zc]);
    }

    // non-atomic partial writes, TRANSPOSED layout [e][d]
    float* kvp = KVpart + ((size_t)bh * KV_SPLIT + chunk) * 4096;
#pragma unroll
    for (int nt = 0; nt < 4; nt++) {
        int d0 = wm * 16 + g;
        int e0 = wn * 32 + nt * 8 + t4 * 2;
        kvp[e0 * HD + d0]           = acc[nt][0];
        kvp[(e0 + 1) * HD + d0]     = acc[nt][1];
        kvp[e0 * HD + d0 + 8]       = acc[nt][2];
        kvp[(e0 + 1) * HD + d0 + 8] = acc[nt][3];
    }
    Zred[tid >> 6][zc] = z;
    __syncthreads();
    if (tid < 64)
        Zpart[((size_t)bh * KV_SPLIT + chunk) * 64 + tid] =
            Zred[0][tid] + Zred[1][tid] + Zred[2][tid] + Zred[3][tid];
}

// ---------------- attn via mma (unchanged) -----------------------------------
constexpr int ROWQ = 72;

__global__ __launch_bounds__(256)
void attn_mma_kernel(const __half* __restrict__ Qmat, const __half* __restrict__ KVZ,
                     __half* __restrict__ Out, int seq)
{
    const int bh = blockIdx.x;
    const int b = bh / NH, h = bh % NH;
    const int n0 = blockIdx.y * 128;
    const int tid  = threadIdx.x;
    const int lane = tid & 31;
    const int warp = tid >> 5;
    const int g = lane >> 2, t4 = lane & 3;

    __shared__ __align__(16) __half Qs[128][ROWQ];
    __shared__ __align__(16) __half Bs[80][ROWQ];

    for (int i = tid; i < 8 * ROWQ; i += 256)
        Bs[72 + i / ROWQ][i % ROWQ] = __ushort_as_half(0);

    const __half* kvzp = KVZ + (size_t)bh * 72 * 64;
#pragma unroll
    for (int l = 0; l < 3; l++) {
        int c = tid + 256 * l;
        if (c < 576) {
            int r = c >> 3, ck = (c & 7) * 8;
            *(uint4*)&Bs[r][ck] = *(const uint4*)&kvzp[r * 64 + ck];
        }
    }

    const size_t base = ((size_t)b * seq) * DIMD + h * HD;
#pragma unroll
    for (int l = 0; l < 4; l++) {
        int c = tid + 256 * l;
        int r = c >> 3, ck = (c & 7) * 8;
        *(uint4*)&Qs[r][ck] = *(const uint4*)&Qmat[base + (size_t)(n0 + r) * DIMD + ck];
    }
    __syncthreads();

    const int a_r = (lane & 7) + ((lane >> 3) & 1) * 8;
    const int a_k = ((lane >> 4) & 1) * 8;
    const uint32_t a_off = (uint32_t)(((warp * 16 + a_r) * ROWQ + a_k) * 2);
    const int b_r = (lane & 7) + ((lane >> 4) & 1) * 8;
    const int b_k = ((lane >> 3) & 1) * 8;
    const uint32_t b_off = (uint32_t)((b_r * ROWQ + b_k) * 2);

    const uint32_t qs_base = smem_u32(&Qs[0][0]);
    const uint32_t bs_base = smem_u32(&Bs[0][0]);

    float acc[9][4];
#pragma unroll
    for (int nt = 0; nt < 9; nt++)
#pragma unroll
        for (int r = 0; r < 4; r++) acc[nt][r] = 0.0f;

#pragma unroll
    for (int ks = 0; ks < 4; ks++) {
        uint32_t ar[4], br[5][4];
        LDSM_X4(ar[0], ar[1], ar[2], ar[3], qs_base + a_off + ks * 32);
#pragma unroll
        for (int q = 0; q < 5; q++)
            LDSM_X4(br[q][0], br[q][1], br[q][2], br[q][3],
                    bs_base + b_off + q * (16 * ROWQ * 2) + ks * 32);
#pragma unroll
        for (int nt = 0; nt < 9; nt++)
            mma_f16(acc[nt], ar,
                    br[nt >> 1][(nt & 1) * 2],
                    br[nt >> 1][(nt & 1) * 2 + 1]);
    }

    float nrm0 = __shfl_sync(0xffffffffu, acc[8][0], lane & ~3);
    float nrm1 = __shfl_sync(0xffffffffu, acc[8][2], lane & ~3);
    float inv0 = 1.0f / (nrm0 + 1e-6f);
    float inv1 = 1.0f / (nrm1 + 1e-6f);

    int row0 = n0 + warp * 16 + g;
    __half* op0 = Out + base + (size_t)row0 * DIMD;
    __half* op1 = Out + base + (size_t)(row0 + 8) * DIMD;
#pragma unroll
    for (int nt = 0; nt < 8; nt++) {
        int e = nt * 8 + t4 * 2;
        *(__half2*)(op0 + e) = __floats2half2_rn(acc[nt][0] * inv0, acc[nt][1] * inv0);
        *(__half2*)(op1 + e) = __floats2half2_rn(acc[nt][2] * inv1, acc[nt][3] * inv1);
    }
}

// ---------------- launcher --------------------------------------------------
extern "C" void kernel_launch(void* const* d_in, const int* in_sizes, int n_in,
                              void* d_out, int out_size)
{
    const float* x  = (const float*)d_in[0];
    const float* Wq = (const float*)d_in[1];
    const float* bq = (const float*)d_in[2];
    const float* Wk = (const float*)d_in[3];
    const float* bk = (const float*)d_in[4];
    const float* Wv = (const float*)d_in[5];
    const float* bv = (const float*)d_in[6];
    const float* Wo = (const float*)d_in[7];
    const float* bo = (const float*)d_in[8];

    const int M   = in_sizes[0] / DIMD;   // 16384
    const int B   = 4;
    const int seq = M / B;                // 4096

    __half *Xh, *Wh, *Qh, *Kh, *Vh, *Ah, *KVZh;
    float *KVpp, *Zpp;
    cudaGetSymbolAddress((void**)&Xh,   g_Xh);
    cudaGetSymbolAddress((void**)&Wh,   g_Wh);
    cudaGetSymbolAddress((void**)&Qh,   g_Qh);
    cudaGetSymbolAddress((void**)&Kh,   g_Kh);
    cudaGetSymbolAddress((void**)&Vh,   g_Vh);
    cudaGetSymbolAddress((void**)&Ah,   g_Ah);
    cudaGetSymbolAddress((void**)&KVZh, g_KVZ);
    cudaGetSymbolAddress((void**)&KVpp, g_KVpart);
    cudaGetSymbolAddress((void**)&Zpp,  g_Zpart);

    cudaFuncSetAttribute(qkv_kernel, cudaFuncAttributeMaxDynamicSharedMemorySize, SMEM_GEMM);
    cudaFuncSetAttribute(out_kernel, cudaFuncAttributeMaxDynamicSharedMemorySize, SMEM_GEMM);

    // 0: convert inputs to fp16 (float4-wide; 5242880 threads)
    cvt_kernel<<<5242880 / 256, 256>>>(x, Wq, Wk, Wv, Wo, Xh, Wh);

    // 1: fused Q/K/V projections (phi fused into Q,K)
    qkv_kernel<<<dim3(DIMD / BN, M / BM, 3), GTHREADS, SMEM_GEMM>>>(
        Xh, Wh, bq, bk, bv, Qh, Kh, Vh);

    // 2: KV state + Z via tensor cores (cp.async double-buffered)
    kv_mma_kernel<<<B * NH * KV_SPLIT, 256>>>(Kh, Vh, KVpp, Zpp, seq);

    // 3: build KVZ fp16 (coalesced partial reduction)
    kvz_kernel<<<(64 * 72 * 64 + 255) / 256, 256>>>(KVpp, Zpp, KVZh);

    // 4: attention apply + normalization via tensor cores
    attn_mma_kernel<<<dim3(B * NH, seq / 128), 256>>>(Qh, KVZh, Ah, seq);

    // 5: output projection -> d_out (fp32)
    out_kernel<<<dim3(DIMD / BN, M / BM), GTHREADS, SMEM_GEMM>>>(Ah, Wh, bo, (float*)d_out);
}